// round 16
// baseline (speedup 1.0000x reference)
#include <cuda_runtime.h>
#include <cuda_bf16.h>
#include <cuda_fp16.h>
#include <math.h>
#include <stdint.h>

#define Bc 4
#define Tc 2048
#define Cc 2048
#define Hc 128
#define Ec 16
#define Nc (Bc*Tc)
#define GT 4
#define KVS 4

// ---------------- device scratch ----------------
__device__ float g_q[Nc*Hc];
__device__ float g_k[Nc*Hc];
__device__ float g_v[Nc*Hc];
__device__ int   g_cnt[Ec];
__device__ int   g_tok[Ec*Nc];
__device__ float g_w[Ec*Nc];
__device__ float g_wninv[Ec];
__device__ float g_sig[Ec];

__device__ __half xhi[(size_t)Nc*Cc], xlo[(size_t)Nc*Cc];
__device__ __half pqh[(size_t)Ec*Hc*Cc];
__device__ __half pkh[(size_t)Ec*Hc*Cc];
__device__ __half pvh[(size_t)Ec*Hc*Cc];
__device__ __half poh[(size_t)Ec*Cc*Hc];
__device__ __half g_ahi[Nc*Hc], g_alo[Nc*Hc];
__device__ __nv_bfloat16 qshi[Nc*Hc], qslo[Nc*Hc];
__device__ __nv_bfloat16 kshi[Nc*Hc], kslo[Nc*Hc];
__device__ __nv_bfloat16 vshi[Nc*Hc], vslo[Nc*Hc];
__device__ float g_oa[KVS][Nc*Hc];
__device__ float g_mm[KVS][Nc], g_ll[KVS][Nc];
__device__ float g_cos[Tc*64], g_sin[Tc*64];

// ---------------- helpers ----------------
__device__ __forceinline__ uint32_t smem_u32(const void* p) {
    uint32_t a;
    asm("{ .reg .u64 t; cvta.to.shared.u64 t, %1; cvt.u32.u64 %0, t; }" : "=r"(a) : "l"(p));
    return a;
}
__device__ __forceinline__ void ldm4(uint32_t* r, uint32_t a) {
    asm volatile("ldmatrix.sync.aligned.m8n8.x4.shared.b16 {%0,%1,%2,%3}, [%4];"
        : "=r"(r[0]), "=r"(r[1]), "=r"(r[2]), "=r"(r[3]) : "r"(a));
}
__device__ __forceinline__ void ldm4t(uint32_t* r, uint32_t a) {
    asm volatile("ldmatrix.sync.aligned.m8n8.x4.trans.shared.b16 {%0,%1,%2,%3}, [%4];"
        : "=r"(r[0]), "=r"(r[1]), "=r"(r[2]), "=r"(r[3]) : "r"(a));
}
__device__ __forceinline__ void mma16816(float* d, const uint32_t* a, const uint32_t* b) {
    asm volatile("mma.sync.aligned.m16n8k16.row.col.f32.bf16.bf16.f32 "
        "{%0,%1,%2,%3},{%4,%5,%6,%7},{%8,%9},{%0,%1,%2,%3};"
        : "+f"(d[0]), "+f"(d[1]), "+f"(d[2]), "+f"(d[3])
        : "r"(a[0]), "r"(a[1]), "r"(a[2]), "r"(a[3]), "r"(b[0]), "r"(b[1]));
}
__device__ __forceinline__ void mma16816h(float* d, const uint32_t* a, const uint32_t* b) {
    asm volatile("mma.sync.aligned.m16n8k16.row.col.f32.f16.f16.f32 "
        "{%0,%1,%2,%3},{%4,%5,%6,%7},{%8,%9},{%0,%1,%2,%3};"
        : "+f"(d[0]), "+f"(d[1]), "+f"(d[2]), "+f"(d[3])
        : "r"(a[0]), "r"(a[1]), "r"(a[2]), "r"(a[3]), "r"(b[0]), "r"(b[1]));
}
__device__ __forceinline__ void cpa(uint32_t dst, const void* src, int zf) {
    asm volatile("cp.async.cg.shared.global [%0], [%1], 16, %2;"
        :: "r"(dst), "l"((unsigned long long)__cvta_generic_to_global(src)), "r"(zf) : "memory");
}
__device__ __forceinline__ void red2(float* p, float x, float y) {
    asm volatile("red.global.add.v2.f32 [%0], {%1,%2};"
        :: "l"((unsigned long long)__cvta_generic_to_global(p)), "f"(x), "f"(y) : "memory");
}
#define CP_COMMIT asm volatile("cp.async.commit_group;" ::: "memory")
#define CP_WAIT0  asm volatile("cp.async.wait_group 0;" ::: "memory")

// ---------------- prep: per-expert sim norms (parallel) ----------------
__global__ void k_z0(const float* __restrict__ sim, const float* __restrict__ gates) {
    int e = blockIdx.x;
    int tid = threadIdx.x;
    float s = 0.f;
    for (int i = tid; i < Cc; i += 256) {
        float v = sim[(size_t)i*Ec + e];
        s += v*v;
    }
    __shared__ float red[8];
    int w = tid >> 5, lane = tid & 31;
    #pragma unroll
    for (int o = 16; o; o >>= 1) s += __shfl_xor_sync(0xffffffffu, s, o);
    if (lane == 0) red[w] = s;
    __syncthreads();
    if (tid == 0) {
        float t = 0.f;
        #pragma unroll
        for (int i = 0; i < 8; i++) t += red[i];
        g_wninv[e] = 1.0f / fmaxf(sqrtf(t), 1e-12f);
        g_sig[e] = 1.0f / (1.0f + expf(-gates[e]));
        g_cnt[e] = 0;
    }
}

// ---------------- big zeroing ----------------
__global__ void k_init(float* __restrict__ out) {
    int i = blockIdx.x * blockDim.x + threadIdx.x;
    int stride = gridDim.x * blockDim.x;
    float4 z = make_float4(0.f, 0.f, 0.f, 0.f);
    for (int j = i; j < Nc*Cc/4; j += stride) ((float4*)out)[j] = z;
    for (int j = i; j < Nc*Hc/4; j += stride) {
        ((float4*)g_q)[j] = z;
        ((float4*)g_k)[j] = z;
        ((float4*)g_v)[j] = z;
    }
}

// ---------------- rope table ----------------
__global__ void k_tab(const int* __restrict__ pid) {
    int idx = blockIdx.x * blockDim.x + threadIdx.x;
    int p = idx >> 6;
    int i = idx & 63;
    int t = pid[p];
    float ang = (float)t * exp2f(-(float)i * (13.28771237954945f / 64.0f));
    float s, c;
    sincosf(ang, &s, &c);
    g_cos[idx] = c;
    g_sin[idx] = s;
}

// ---------------- x -> fp16 hi/lo split (overlapped) ----------------
__global__ void k_xsplit(const float* __restrict__ x) {
    #pragma unroll
    for (int j = 0; j < 4; j++) {
        int i = (blockIdx.x*4 + j)*256 + threadIdx.x;
        float4 v = ((const float4*)x)[i];
        __half h0 = __float2half_rn(v.x), h1 = __float2half_rn(v.y);
        __half h2 = __float2half_rn(v.z), h3 = __float2half_rn(v.w);
        ((__half2*)xhi)[i*2]   = __half2(h0, h1);
        ((__half2*)xhi)[i*2+1] = __half2(h2, h3);
        __half2 l01(__float2half_rn(v.x - __half2float(h0)), __float2half_rn(v.y - __half2float(h1)));
        __half2 l23(__float2half_rn(v.z - __half2float(h2)), __float2half_rn(v.w - __half2float(h3)));
        ((__half2*)xlo)[i*2]   = l01;
        ((__half2*)xlo)[i*2+1] = l23;
    }
}

// ---------------- gating: 2 token-groups per block (sim L1 reuse) ----------------
__global__ void k_gate(const float* __restrict__ x, const float* __restrict__ sim) {
    __shared__ float red[8][GT*Ec + GT];
    int wid = threadIdx.x >> 5, lane = threadIdx.x & 31;
    #pragma unroll 1
    for (int g = 0; g < 2; g++) {
        int n0 = blockIdx.x * (2*GT) + g*GT;
        float dot[GT][Ec];
        float ss[GT];
        #pragma unroll
        for (int j = 0; j < GT; j++) {
            ss[j] = 0.f;
            #pragma unroll
            for (int e = 0; e < Ec; e++) dot[j][e] = 0.f;
        }
        for (int i = threadIdx.x; i < Cc; i += 256) {
            float xv[GT];
            #pragma unroll
            for (int j = 0; j < GT; j++) {
                xv[j] = x[(size_t)(n0 + j)*Cc + i];
                ss[j] += xv[j]*xv[j];
            }
            const float4* s4 = (const float4*)(sim + (size_t)i*Ec);
            #pragma unroll
            for (int q = 0; q < 4; q++) {
                float4 sv = s4[q];
                #pragma unroll
                for (int j = 0; j < GT; j++) {
                    dot[j][q*4+0] += xv[j]*sv.x;
                    dot[j][q*4+1] += xv[j]*sv.y;
                    dot[j][q*4+2] += xv[j]*sv.z;
                    dot[j][q*4+3] += xv[j]*sv.w;
                }
            }
        }
        #pragma unroll
        for (int j = 0; j < GT; j++) {
            #pragma unroll
            for (int e = 0; e < Ec; e++) {
                float v = dot[j][e];
                #pragma unroll
                for (int o = 16; o; o >>= 1) v += __shfl_xor_sync(0xffffffffu, v, o);
                if (lane == 0) red[wid][j*Ec + e] = v;
            }
            float v = ss[j];
            #pragma unroll
            for (int o = 16; o; o >>= 1) v += __shfl_xor_sync(0xffffffffu, v, o);
            if (lane == 0) red[wid][GT*Ec + j] = v;
        }
        __syncthreads();
        if (threadIdx.x < GT*Ec + GT) {
            float s = 0.f;
            #pragma unroll
            for (int w = 0; w < 8; w++) s += red[w][threadIdx.x];
            red[0][threadIdx.x] = s;
        }
        __syncthreads();
        if (threadIdx.x < GT) {
            int j = threadIdx.x;
            int n = n0 + j;
            float xin = rsqrtf(fmaxf(red[0][GT*Ec + j], 1e-24f));
            float logitv[Ec], gatedv[Ec];
            int act = 0;
            #pragma unroll
            for (int e = 0; e < Ec; e++) {
                float lg = red[0][j*Ec + e] * xin * g_wninv[e] - g_sig[e];
                logitv[e] = lg;
                gatedv[e] = fmaxf(lg, 0.f);
                act += (lg > 0.f) ? 1 : 0;
            }
            unsigned mask = 0u;
            if (act > 0) {
                #pragma unroll
                for (int e = 0; e < Ec; e++) if (logitv[e] > 0.f) mask |= (1u << e);
            } else {
                int i1 = 0;
                #pragma unroll
                for (int e = 1; e < Ec; e++) if (logitv[e] > logitv[i1]) i1 = e;
                int i2 = (i1 == 0) ? 1 : 0;
                #pragma unroll
                for (int e = 0; e < Ec; e++)
                    if (e != i1 && logitv[e] > logitv[i2]) i2 = e;
                mask = (1u << i1) | (1u << i2);
            }
            float m = -1e30f;
            #pragma unroll
            for (int e = 0; e < Ec; e++) if ((mask >> e) & 1u) m = fmaxf(m, gatedv[e]);
            float ssum = 0.f;
            float ex[Ec];
            #pragma unroll
            for (int e = 0; e < Ec; e++) {
                float t = ((mask >> e) & 1u) ? expf(gatedv[e] - m) : 0.f;
                ex[e] = t;
                ssum += t;
            }
            float sinv = 1.f / ssum;
            #pragma unroll
            for (int e = 0; e < Ec; e++) {
                if ((mask >> e) & 1u) {
                    int p = atomicAdd(&g_cnt[e], 1);
                    g_tok[e*Nc + p] = n;
                    g_w[e*Nc + p]   = ex[e] * sinv;
                }
            }
        }
        __syncthreads();
    }
}

// ---------------- weight conversions (fp16 single) ----------------
__global__ void k_conv(const float* __restrict__ qp, const float* __restrict__ kp,
                       const float* __restrict__ vp, const float* __restrict__ op) {
    int y = blockIdx.y;
    __shared__ float tile[32][33];
    int e = blockIdx.x >> 8;
    int t = blockIdx.x & 255;
    int c0 = (t >> 2) * 32, h0 = (t & 3) * 32;
    int tx = threadIdx.x & 31, ty = threadIdx.x >> 5;
    if (y < 3) {
        const float* src = (y == 0) ? qp : (y == 1) ? kp : vp;
        __half* dh = (y == 0) ? pqh : (y == 1) ? pkh : pvh;
        #pragma unroll
        for (int cy = 0; cy < 32; cy += 8)
            tile[ty + cy][tx] = src[((size_t)e*Cc + c0 + ty + cy)*Hc + h0 + tx];
        __syncthreads();
        #pragma unroll
        for (int hy = 0; hy < 32; hy += 8) {
            float v = tile[tx][ty + hy];
            dh[((size_t)e*Hc + h0 + ty + hy)*Cc + c0 + tx] = __float2half_rn(v);
        }
    } else {
        #pragma unroll
        for (int hy = 0; hy < 32; hy += 8)
            tile[ty + hy][tx] = op[((size_t)e*Hc + h0 + ty + hy)*Cc + c0 + tx];
        __syncthreads();
        #pragma unroll
        for (int cy = 0; cy < 32; cy += 8) {
            float v = tile[tx][ty + cy];
            poh[((size_t)e*Cc + c0 + ty + cy)*Hc + h0 + tx] = __float2half_rn(v);
        }
    }
}

// ---------------- fp16 2-product grouped QKV GEMM ----------------
#define STG_A 10240
#define STG_SZ (3*STG_A)
__global__ __launch_bounds__(256, 2) void k_qkv_mma() {
    extern __shared__ char smem[];
    int e = blockIdx.y;
    int cnt = g_cnt[e];
    int m0 = blockIdx.x * 128;
    if (m0 >= cnt) return;
    int sel = blockIdx.z % 3;
    int ksp = blockIdx.z / 3;
    const __half* BH;
    float* dst;
    if (sel == 0)      { BH = pqh; dst = g_q; }
    else if (sel == 1) { BH = pkh; dst = g_k; }
    else               { BH = pvh; dst = g_v; }

    int* sTok = (int*)smem;
    float* sW = (float*)(smem + 512);
    uint32_t tiles = smem_u32(smem) + 1024;
    int tid = threadIdx.x;

    if (tid < 128) {
        int i = m0 + tid;
        if (i < cnt) { sTok[tid] = g_tok[e*Nc + i]; sW[tid] = g_w[e*Nc + i]; }
        else         { sTok[tid] = -1;               sW[tid] = 0.f; }
    }
    __syncthreads();

    int lrow = tid >> 1, lc = (tid & 1) * 2;
    int ltok = sTok[lrow];
    int zf = (ltok >= 0) ? 16 : 0;
    int kbase0 = ksp * (Cc/2);
    const __half* aHp = xhi + (size_t)(ltok < 0 ? 0 : ltok)*Cc + kbase0 + lc*8;
    const __half* aLp = xlo + (size_t)(ltok < 0 ? 0 : ltok)*Cc + kbase0 + lc*8;
    const __half* bHp = BH + ((size_t)e*Hc + lrow)*Cc + kbase0 + lc*8;
    uint32_t loff = lrow*80 + lc*16;

    auto loadStage = [&](int s) {
        uint32_t base = tiles + (s & 1) * STG_SZ;
        int k0 = s * 32;
        cpa(base + loff,                 aHp + k0, zf);
        cpa(base + loff + 16,            aHp + k0 + 8, zf);
        cpa(base + STG_A + loff,         aLp + k0, zf);
        cpa(base + STG_A + loff + 16,    aLp + k0 + 8, zf);
        cpa(base + 2*STG_A + loff,       bHp + k0, 16);
        cpa(base + 2*STG_A + loff + 16,  bHp + k0 + 8, 16);
        CP_COMMIT;
    };

    int w = tid >> 5, lane = tid & 31;
    int wr = w & 3, wc = w >> 2;
    int aRowL = wr*32 + (lane & 15);
    int aCB  = lane >> 4;
    int bRowL = (lane & 7) + ((lane >> 4) << 3);
    int bCB  = (lane >> 3) & 1;

    float d[2][8][4];
    #pragma unroll
    for (int mt = 0; mt < 2; mt++)
        #pragma unroll
        for (int nt = 0; nt < 8; nt++)
            #pragma unroll
            for (int q = 0; q < 4; q++) d[mt][nt][q] = 0.f;

    const int NS = (Cc/2)/32;
    loadStage(0);
    for (int s = 0; s < NS; s++) {
        CP_WAIT0;
        __syncthreads();
        if (s + 1 < NS) loadStage(s + 1);
        uint32_t base = tiles + (s & 1)*STG_SZ;
        uint32_t bbase = base + 2*STG_A;
        #pragma unroll
        for (int kc = 0; kc < 2; kc++) {
            uint32_t ah[2][4], al[2][4];
            #pragma unroll
            for (int mt = 0; mt < 2; mt++) {
                int r = aRowL + mt*16;
                uint32_t ad = base + r*80 + (((kc << 1) + aCB) << 4);
                ldm4(ah[mt], ad);
                ldm4(al[mt], ad + STG_A);
            }
            #pragma unroll
            for (int np = 0; np < 4; np++) {
                int r = wc*64 + np*16 + bRowL;
                uint32_t bd = bbase + r*80 + (((kc << 1) + bCB) << 4);
                uint32_t bh[4];
                ldm4(bh, bd);
                #pragma unroll
                for (int mt = 0; mt < 2; mt++)
                    #pragma unroll
                    for (int i = 0; i < 2; i++)
                        mma16816h(d[mt][np*2 + i], ah[mt], bh + 2*i);
                #pragma unroll
                for (int mt = 0; mt < 2; mt++)
                    #pragma unroll
                    for (int i = 0; i < 2; i++)
                        mma16816h(d[mt][np*2 + i], al[mt], bh + 2*i);
            }
        }
    }

    #pragma unroll
    for (int mt = 0; mt < 2; mt++) {
        int r0 = wr*32 + mt*16 + (lane >> 2);
        int r1 = r0 + 8;
        int t0 = sTok[r0], t1 = sTok[r1];
        float w0 = sW[r0], w1 = sW[r1];
        #pragma unroll
        for (int nt = 0; nt < 8; nt++) {
            int col = wc*64 + nt*8 + (lane & 3)*2;
            if (t0 >= 0) red2(dst + (size_t)t0*Hc + col, d[mt][nt][0]*w0, d[mt][nt][1]*w0);
            if (t1 >= 0) red2(dst + (size_t)t1*Hc + col, d[mt][nt][2]*w1, d[mt][nt][3]*w1);
        }
    }
}

// ---------------- RoPE (table lookup) + bf16 hi/lo split ----------------
__global__ void k_rope() {
    int idx = blockIdx.x * blockDim.x + threadIdx.x;
    if (idx >= Nc*64) return;
    int n = idx >> 6;
    int i = idx & 63;
    int p = n & (Tc - 1);
    float c = g_cos[p*64 + i];
    float s = g_sin[p*64 + i];
    size_t base = (size_t)n * Hc;
    float q0 = g_q[base + i], q1 = g_q[base + i + 64];
    float k0 = g_k[base + i], k1 = g_k[base + i + 64];
    float v0 = g_v[base + i], v1 = g_v[base + i + 64];
    float qa = q0*c - q1*s, qb = q1*c + q0*s;
    float ka = k0*c - k1*s, kb = k1*c + k0*s;
    __nv_bfloat16 h;
    h = __float2bfloat16_rn(qa); qshi[base+i] = h;    qslo[base+i]    = __float2bfloat16_rn(qa - __bfloat162float(h));
    h = __float2bfloat16_rn(qb); qshi[base+i+64] = h; qslo[base+i+64] = __float2bfloat16_rn(qb - __bfloat162float(h));
    h = __float2bfloat16_rn(ka); kshi[base+i] = h;    kslo[base+i]    = __float2bfloat16_rn(ka - __bfloat162float(h));
    h = __float2bfloat16_rn(kb); kshi[base+i+64] = h; kslo[base+i+64] = __float2bfloat16_rn(kb - __bfloat162float(h));
    h = __float2bfloat16_rn(v0); vshi[base+i] = h;    vslo[base+i]    = __float2bfloat16_rn(v0 - __bfloat162float(h));
    h = __float2bfloat16_rn(v1); vshi[base+i+64] = h; vslo[base+i+64] = __float2bfloat16_rn(v1 - __bfloat162float(h));
}

// ---------------- MMA flash attention, split-KV x4, LPT block order ----------------
__global__ __launch_bounds__(256, 1) void k_attn_mma() {
    extern __shared__ char smem[];
    int qb = (gridDim.x - 1) - blockIdx.x;   // longest blocks first (LPT)
    int b  = blockIdx.y;
    int zz = blockIdx.z;
    int q0 = qb * 128;
    uint32_t sQ = smem_u32(smem);
    uint32_t sKV = sQ + 65536;
    int tid = threadIdx.x, w = tid >> 5, lane = tid & 31;

    int nkt_tot = 2*qb + 2;
    int kt0 = (nkt_tot * zz) / KVS;
    int kt1 = (nkt_tot * (zz + 1)) / KVS;

    {
        int qrow = tid >> 1;
        int c4 = (tid & 1) * 4;
        const __nv_bfloat16* qh = qshi + ((size_t)(b*Tc + q0 + qrow))*Hc;
        const __nv_bfloat16* ql = qslo + ((size_t)(b*Tc + q0 + qrow))*Hc;
        #pragma unroll
        for (int sub = 0; sub < 2; sub++) {
            #pragma unroll
            for (int u = 0; u < 4; u++) {
                int c = c4 + u;
                uint32_t off = sub*16384 + qrow*128 + ((c ^ (qrow & 7)) << 4);
                cpa(sQ + off,         qh + sub*64 + c*8, 16);
                cpa(sQ + 32768 + off, ql + sub*64 + c*8, 16);
            }
        }
        CP_COMMIT;
    }

    int krow = tid >> 2;
    int part = tid & 3;
    const __nv_bfloat16* kvsrc =
        (part == 0) ? kshi : (part == 1) ? kslo : (part == 2) ? vshi : vslo;
    auto loadKV = [&](int kt) {
        uint32_t base = sKV + (kt & 1)*65536 + part*16384;
        const __nv_bfloat16* src = kvsrc + ((size_t)(b*Tc + kt*64 + krow))*Hc;
        #pragma unroll
        for (int sub = 0; sub < 2; sub++) {
            #pragma unroll
            for (int c = 0; c < 8; c++) {
                cpa(base + sub*8192 + krow*128 + ((c ^ (krow & 7)) << 4),
                    src + sub*64 + c*8, 16);
            }
        }
        CP_COMMIT;
    };

    const float scale = 0.08838834764831845f;
    float o[16][4];
    #pragma unroll
    for (int nt = 0; nt < 16; nt++)
        #pragma unroll
        for (int q = 0; q < 4; q++) o[nt][q] = 0.f;
    float m0 = -1e30f, m1 = -1e30f, l0 = 0.f, l1 = 0.f;

    int aRow = w*16 + (lane & 15);
    int aCB  = lane >> 4;
    int bRow = (lane & 7) + ((lane >> 4) << 3);
    int bCB  = (lane >> 3) & 1;
    int rowg0 = q0 + w*16 + (lane >> 2);
    int rowg1 = rowg0 + 8;

    if (kt0 < kt1) loadKV(kt0);
    for (int kt = kt0; kt < kt1; kt++) {
        CP_WAIT0;
        __syncthreads();
        if (kt + 1 < kt1) loadKV(kt + 1);
        uint32_t kbase = sKV + (kt & 1)*65536;

        float sAcc[8][4];
        #pragma unroll
        for (int nt = 0; nt < 8; nt++)
            #pragma unroll
            for (int q = 0; q < 4; q++) sAcc[nt][q] = 0.f;
        #pragma unroll
        for (int sub = 0; sub < 2; sub++) {
            #pragma unroll
            for (int kc = 0; kc < 4; kc++) {
                uint32_t ah[4], al[4];
                uint32_t ad = sQ + sub*16384 + aRow*128 + ((((kc << 1) + aCB) ^ (aRow & 7)) << 4);
                ldm4(ah, ad);
                ldm4(al, ad + 32768);
                #pragma unroll
                for (int nb = 0; nb < 2; nb++) {
                    uint32_t bh0[4], bl0[4], bh1[4], bl1[4];
                    int r0 = bRow + (2*nb)*16;
                    int r1 = bRow + (2*nb + 1)*16;
                    uint32_t bd0 = kbase + sub*8192 + r0*128 + ((((kc << 1) + bCB) ^ (r0 & 7)) << 4);
                    uint32_t bd1 = kbase + sub*8192 + r1*128 + ((((kc << 1) + bCB) ^ (r1 & 7)) << 4);
                    ldm4(bh0, bd0);
                    ldm4(bl0, bd0 + 16384);
                    ldm4(bh1, bd1);
                    ldm4(bl1, bd1 + 16384);
                    float* a0 = sAcc[4*nb + 0];
                    float* a1 = sAcc[4*nb + 1];
                    float* a2 = sAcc[4*nb + 2];
                    float* a3 = sAcc[4*nb + 3];
                    mma16816(a0, ah, bh0 + 0); mma16816(a1, ah, bh0 + 2);
                    mma16816(a2, ah, bh1 + 0); mma16816(a3, ah, bh1 + 2);
                    mma16816(a0, ah, bl0 + 0); mma16816(a1, ah, bl0 + 2);
                    mma16816(a2, ah, bl1 + 0); mma16816(a3, ah, bl1 + 2);
                    mma16816(a0, al, bh0 + 0); mma16816(a1, al, bh0 + 2);
                    mma16816(a2, al, bh1 + 0); mma16816(a3, al, bh1 + 2);
                }
            }
        }

        int k0 = kt*64;
        bool diag = (kt >= 2*qb);
        #pragma unroll
        for (int nt = 0; nt < 8; nt++) {
            int cbase = k0 + nt*8 + (lane & 3)*2;
            #pragma unroll
            for (int q = 0; q < 4; q++) {
                float v = sAcc[nt][q] * scale;
                if (diag) {
                    int col = cbase + (q & 1);
                    int row = (q < 2) ? rowg0 : rowg1;
                    if (col > row) v = -1e30f;
                }
                sAcc[nt][q] = v;
            }
        }

        float rm0 = -1e30f, rm1 = -1e30f;
        #pragma unroll
        for (int nt = 0; nt < 8; nt++) {
            rm0 = fmaxf(rm0, fmaxf(sAcc[nt][0], sAcc[nt][1]));
            rm1 = fmaxf(rm1, fmaxf(sAcc[nt][2], sAcc[nt][3]));
        }
        #pragma unroll
        for (int off = 1; off < 4; off <<= 1) {
            rm0 = fmaxf(rm0, __shfl_xor_sync(0xffffffffu, rm0, off));
            rm1 = fmaxf(rm1, __shfl_xor_sync(0xffffffffu, rm1, off));
        }
        float mn0 = fmaxf(m0, rm0), mn1 = fmaxf(m1, rm1);
        float al0 = __expf(m0 - mn0), al1 = __expf(m1 - mn1);
        float ps0 = 0.f, ps1 = 0.f;
        #pragma unroll
        for (int nt = 0; nt < 8; nt++) {
            sAcc[nt][0] = __expf(sAcc[nt][0] - mn0);
            sAcc[nt][1] = __expf(sAcc[nt][1] - mn0);
            sAcc[nt][2] = __expf(sAcc[nt][2] - mn1);
            sAcc[nt][3] = __expf(sAcc[nt][3] - mn1);
            ps0 += sAcc[nt][0] + sAcc[nt][1];
            ps1 += sAcc[nt][2] + sAcc[nt][3];
        }
        #pragma unroll
        for (int off = 1; off < 4; off <<= 1) {
            ps0 += __shfl_xor_sync(0xffffffffu, ps0, off);
            ps1 += __shfl_xor_sync(0xffffffffu, ps1, off);
        }
        l0 = l0*al0 + ps0;
        l1 = l1*al1 + ps1;
        m0 = mn0;
        m1 = mn1;
        #pragma unroll
        for (int nt = 0; nt < 16; nt++) {
            o[nt][0] *= al0; o[nt][1] *= al0;
            o[nt][2] *= al1; o[nt][3] *= al1;
        }

        #pragma unroll
        for (int ks = 0; ks < 4; ks++) {
            uint32_t ph[4], pl[4];
            #pragma unroll
            for (int hq = 0; hq < 2; hq++) {
                int nt = 2*ks + hq;
                float p0 = sAcc[nt][0], p1 = sAcc[nt][1];
                float p2 = sAcc[nt][2], p3 = sAcc[nt][3];
                __nv_bfloat16 b0 = __float2bfloat16_rn(p0), b1 = __float2bfloat16_rn(p1);
                __nv_bfloat16 b2 = __float2bfloat16_rn(p2), b3 = __float2bfloat16_rn(p3);
                __nv_bfloat162 hh01(b0, b1), hh23(b2, b3);
                ph[0 + hq*2] = *(uint32_t*)&hh01;
                ph[1 + hq*2] = *(uint32_t*)&hh23;
                __nv_bfloat162 ll01(__float2bfloat16_rn(p0 - __bfloat162float(b0)),
                                    __float2bfloat16_rn(p1 - __bfloat162float(b1)));
                __nv_bfloat162 ll23(__float2bfloat16_rn(p2 - __bfloat162float(b2)),
                                    __float2bfloat16_rn(p3 - __bfloat162float(b3)));
                pl[0 + hq*2] = *(uint32_t*)&ll01;
                pl[1 + hq*2] = *(uint32_t*)&ll23;
            }
            int vrow = ks*16 + (lane & 15);
            #pragma unroll
            for (int hp = 0; hp < 4; hp++) {
                int ht0 = 2*hp, ht1 = 2*hp + 1;
                int sub0 = ht0 >> 2, sub1 = ht1 >> 2;
                int cl0 = (ht0 & 3)*2 + (lane >> 4);
                int cl1 = (ht1 & 3)*2 + (lane >> 4);
                uint32_t vd0 = kbase + 32768 + sub0*8192 + vrow*128 + ((cl0 ^ (vrow & 7)) << 4);
                uint32_t vd1 = kbase + 32768 + sub1*8192 + vrow*128 + ((cl1 ^ (vrow & 7)) << 4);
                uint32_t vh0[4], vl0[4], vh1[4], vl1[4];
                ldm4t(vh0, vd0);
                ldm4t(vl0, vd0 + 16384);
                ldm4t(vh1, vd1);
                ldm4t(vl1, vd1 + 16384);
                float* a0 = o[ht0*2 + 0];
                float* a1 = o[ht0*2 + 1];
                float* a2 = o[ht1*2 + 0];
                float* a3 = o[ht1*2 + 1];
                mma16816(a0, ph, vh0 + 0); mma16816(a1, ph, vh0 + 2);
                mma16816(a2, ph, vh1 + 0); mma16816(a3, ph, vh1 + 2);
                mma16816(a0, ph, vl0 + 0); mma16816(a1, ph, vl0 + 2);
                mma16816(a2, ph, vl1 + 0); mma16816(a3, ph, vl1 + 2);
                mma16816(a0, pl, vh0 + 0); mma16816(a1, pl, vh0 + 2);
                mma16816(a2, pl, vh1 + 0); mma16816(a3, pl, vh1 + 2);
            }
        }
    }

    float* oa = g_oa[zz];
    float* gm = g_mm[zz];
    float* gl = g_ll[zz];
    int n0g = b*Tc + rowg0;
    int n1g = b*Tc + rowg1;
    if ((lane & 3) == 0) {
        gm[n0g] = m0; gl[n0g] = l0;
        gm[n1g] = m1; gl[n1g] = l1;
    }
    size_t ga0 = (size_t)n0g*Hc;
    size_t ga1 = (size_t)n1g*Hc;
    #pragma unroll
    for (int nt = 0; nt < 16; nt++) {
        int col = nt*8 + (lane & 3)*2;
        *(float2*)(oa + ga0 + col) = make_float2(o[nt][0], o[nt][1]);
        *(float2*)(oa + ga1 + col) = make_float2(o[nt][2], o[nt][3]);
    }
}

// ---------------- combine split-KV partials (x4) -> fp16 hi/lo ----------------
__global__ void k_combine() {
    int idx = blockIdx.x * blockDim.x + threadIdx.x;
    int n = idx >> 5;
    int c4 = (idx & 31) * 4;
    float mv[KVS], lv[KVS];
    float M = -1e30f;
    #pragma unroll
    for (int z = 0; z < KVS; z++) {
        mv[z] = g_mm[z][n];
        lv[z] = g_ll[z][n];
        M = fmaxf(M, mv[z]);
    }
    float wz[KVS];
    float L = 0.f;
    #pragma unroll
    for (int z = 0; z < KVS; z++) {
        wz[z] = __expf(mv[z] - M);
        L += lv[z]*wz[z];
    }
    float li = 1.0f / L;
    float v0 = 0.f, v1 = 0.f, v2 = 0.f, v3 = 0.f;
    #pragma unroll
    for (int z = 0; z < KVS; z++) {
        float4 oz = *(float4*)(g_oa[z] + (size_t)n*Hc + c4);
        v0 += oz.x*wz[z]; v1 += oz.y*wz[z];
        v2 += oz.z*wz[z]; v3 += oz.w*wz[z];
    }
    v0 *= li; v1 *= li; v2 *= li; v3 *= li;
    __half h0 = __float2half_rn(v0), h1 = __float2half_rn(v1);
    __half h2 = __float2half_rn(v2), h3 = __float2half_rn(v3);
    ((__half2*)(g_ahi + (size_t)n*Hc + c4))[0] = __half2(h0, h1);
    ((__half2*)(g_ahi + (size_t)n*Hc + c4))[1] = __half2(h2, h3);
    __half2 q01(__float2half_rn(v0 - __half2float(h0)), __float2half_rn(v1 - __half2float(h1)));
    __half2 q23(__float2half_rn(v2 - __half2float(h2)), __float2half_rn(v3 - __half2float(h3)));
    ((__half2*)(g_alo + (size_t)n*Hc + c4))[0] = q01;
    ((__half2*)(g_alo + (size_t)n*Hc + c4))[1] = q23;
}

// ---------------- fp16 2-product grouped O-proj GEMM ----------------
__global__ __launch_bounds__(256, 1) void k_oproj_mma(float* __restrict__ out) {
    extern __shared__ char smem[];
    int e = blockIdx.y;
    int cnt = g_cnt[e];
    int m0 = blockIdx.x * 128;
    if (m0 >= cnt) return;
    int nc0 = blockIdx.z * 8, nc1 = nc0 + 8;

    int* sTok = (int*)smem;
    float* sW = (float*)(smem + 512);
    uint32_t tiles = smem_u32(smem) + 1024;
    int tid = threadIdx.x;

    if (tid < 128) {
        int i = m0 + tid;
        if (i < cnt) { sTok[tid] = g_tok[e*Nc + i]; sW[tid] = g_w[e*Nc + i]; }
        else         { sTok[tid] = -1;               sW[tid] = 0.f; }
    }
    __syncthreads();

    int lrow = tid >> 1;
    int lc0 = (tid & 1) * 4;
    int ltok = sTok[lrow];
    int zf = (ltok >= 0) ? 16 : 0;
    uint32_t loff[4];
    #pragma unroll
    for (int u = 0; u < 4; u++) {
        int c = lc0 + u;
        loff[u] = lrow*128 + ((c ^ (lrow & 7)) << 4);
    }
    {
        const __half* aH = g_ahi + (size_t)(ltok < 0 ? 0 : ltok)*Hc;
        const __half* aL = g_alo + (size_t)(ltok < 0 ? 0 : ltok)*Hc;
        #pragma unroll
        for (int kh = 0; kh < 2; kh++) {
            #pragma unroll
            for (int u = 0; u < 4; u++) {
                int c = lc0 + u;
                uint32_t d0 = tiles + kh*16384 + loff[u];
                cpa(d0,         aH + kh*64 + c*8, zf);
                cpa(d0 + 32768, aL + kh*64 + c*8, zf);
            }
        }
        CP_COMMIT;
    }
    const __half* oH = poh + ((size_t)e*Cc + lrow)*Hc;
    auto loadB = [&](int nc) {
        uint32_t base = tiles + 65536 + (nc & 1)*32768;
        size_t ro = (size_t)nc*128*Hc;
        #pragma unroll
        for (int kh = 0; kh < 2; kh++) {
            #pragma unroll
            for (int u = 0; u < 4; u++) {
                int c = lc0 + u;
                cpa(base + kh*16384 + loff[u], oH + ro + kh*64 + c*8, 16);
            }
        }
        CP_COMMIT;
    };

    int w = tid >> 5, lane = tid & 31;
    int wr = w & 3, wc = w >> 2;
    int aRow  = wr*32 + (lane & 15);
    int aCB   = lane >> 4;
    int bRowB = wc*64 + (lane & 7) + ((lane >> 4) << 3);
    int bCB   = (lane >> 3) & 1;

    int et0[2], et1[2];
    float ew0[2], ew1[2];
    #pragma unroll
    for (int mt = 0; mt < 2; mt++) {
        int r0 = wr*32 + mt*16 + (lane >> 2);
        et0[mt] = sTok[r0]; ew0[mt] = sW[r0];
        et1[mt] = sTok[r0 + 8]; ew1[mt] = sW[r0 + 8];
    }

    loadB(nc0);
    for (int nc = nc0; nc < nc1; nc++) {
        CP_WAIT0;
        __syncthreads();
        if (nc + 1 < nc1) loadB(nc + 1);

        float d[2][8][4];
        #pragma unroll
        for (int mt = 0; mt < 2; mt++)
            #pragma unroll
            for (int nt = 0; nt < 8; nt++)
                #pragma unroll
                for (int q = 0; q < 4; q++) d[mt][nt][q] = 0.f;

        uint32_t bbase = tiles + 65536 + (nc & 1)*32768;
        #pragma unroll
        for (int kh = 0; kh < 2; kh++) {
            #pragma unroll
            for (int kc = 0; kc < 4; kc++) {
                uint32_t ah[2][4], al[2][4];
                #pragma unroll
                for (int mt = 0; mt < 2; mt++) {
                    int r = aRow + mt*16;
                    uint32_t ad = tiles + kh*16384 + r*128 + ((((kc << 1) + aCB) ^ (r & 7)) << 4);
                    ldm4(ah[mt], ad);
                    ldm4(al[mt], ad + 32768);
                }
                #pragma unroll
                for (int np = 0; np < 4; np++) {
                    int r = bRowB + np*16;
                    uint32_t bd = bbase + kh*16384 + r*128 + ((((kc << 1) + bCB) ^ (r & 7)) << 4);
                    uint32_t bh[4];
                    ldm4(bh, bd);
                    #pragma unroll
                    for (int mt = 0; mt < 2; mt++)
                        #pragma unroll
                        for (int i = 0; i < 2; i++)
                            mma16816h(d[mt][np*2 + i], ah[mt], bh + 2*i);
                    #pragma unroll
                    for (int mt = 0; mt < 2; mt++)
                        #pragma unroll
                        for (int i = 0; i < 2; i++)
                            mma16816h(d[mt][np*2 + i], al[mt], bh + 2*i);
                }
            }
        }

        #pragma unroll
        for (int mt = 0; mt < 2; mt++) {
            #pragma unroll
            for (int nt = 0; nt < 8; nt++) {
                int col = nc*128 + wc*64 + nt*8 + (lane & 3)*2;
                if (et0[mt] >= 0) red2(out + (size_t)et0[mt]*Cc + col, d[mt][nt][0]*ew0[mt], d[mt][nt][1]*ew0[mt]);
                if (et1[mt] >= 0) red2(out + (size_t)et1[mt]*Cc + col, d[mt][nt][2]*ew1[mt], d[mt][nt][3]*ew1[mt]);
            }
        }
    }
}

// ---------------- launch (stream fork/join overlap) ----------------
extern "C" void kernel_launch(void* const* d_in, const int* in_sizes, int n_in,
                              void* d_out, int out_size) {
    const float* x     = (const float*)d_in[0];
    const int*   pid   = (const int*)  d_in[1];
    const float* sim   = (const float*)d_in[2];
    const float* gates = (const float*)d_in[3];
    const float* qp    = (const float*)d_in[4];
    const float* kp    = (const float*)d_in[5];
    const float* vp    = (const float*)d_in[6];
    const float* op    = (const float*)d_in[7];
    float* out = (float*)d_out;

    const int SMEM_QKV  = 1024 + 2*STG_SZ;
    const int SMEM_OP   = 1024 + 65536 + 65536;
    const int SMEM_ATTN = 65536 + 2*65536;

    static cudaStream_t s1 = nullptr, s2 = nullptr;
    static cudaEvent_t ev0, ev1, ev2;
    if (!s1) {
        cudaStreamCreateWithFlags(&s1, cudaStreamNonBlocking);
        cudaStreamCreateWithFlags(&s2, cudaStreamNonBlocking);
        cudaEventCreateWithFlags(&ev0, cudaEventDisableTiming);
        cudaEventCreateWithFlags(&ev1, cudaEventDisableTiming);
        cudaEventCreateWithFlags(&ev2, cudaEventDisableTiming);
        cudaFuncSetAttribute(k_qkv_mma,   cudaFuncAttributeMaxDynamicSharedMemorySize, SMEM_QKV);
        cudaFuncSetAttribute(k_oproj_mma, cudaFuncAttributeMaxDynamicSharedMemorySize, SMEM_OP);
        cudaFuncSetAttribute(k_attn_mma,  cudaFuncAttributeMaxDynamicSharedMemorySize, SMEM_ATTN);
    }

    // fork
    cudaEventRecord(ev0, 0);
    cudaStreamWaitEvent(s1, ev0, 0);
    cudaStreamWaitEvent(s2, ev0, 0);

    // s1: weight conversion (consumers: qkv, oproj)
    k_conv <<<dim3(4096, 4), 256, 0, s1>>>(qp, kp, vp, op);
    cudaEventRecord(ev1, s1);

    // s2: big zeroing + rope table + x fp16 split
    k_init  <<<2048, 256, 0, s2>>>(out);
    k_xsplit<<<4096, 256, 0, s2>>>(x);
    k_tab   <<<(Tc*64)/256, 256, 0, s2>>>(pid);
    cudaEventRecord(ev2, s2);

    // s0: gating chain
    k_z0   <<<Ec, 256>>>(sim, gates);
    k_gate <<<Nc/(2*GT), 256>>>(x, sim);

    // join
    cudaStreamWaitEvent(0, ev1, 0);
    cudaStreamWaitEvent(0, ev2, 0);

    k_qkv_mma<<<dim3(Nc/128, Ec, 6), 256, SMEM_QKV>>>();
    k_rope <<<(Nc*64)/256, 256>>>();
    k_attn_mma<<<dim3(Tc/128, Bc, KVS), 256, SMEM_ATTN>>>();
    k_combine<<<(Nc*32)/256, 256>>>();
    k_oproj_mma<<<dim3(Nc/128, Ec, 2), 256, SMEM_OP>>>(out);
}

// round 17
// speedup vs baseline: 1.1921x; 1.1921x over previous
#include <cuda_runtime.h>
#include <cuda_bf16.h>
#include <cuda_fp16.h>
#include <math.h>
#include <stdint.h>

#define Bc 4
#define Tc 2048
#define Cc 2048
#define Hc 128
#define Ec 16
#define Nc (Bc*Tc)
#define GT 4
#define KVS 4

// ---------------- device scratch ----------------
__device__ float g_q[Nc*Hc];
__device__ float g_k[Nc*Hc];
__device__ float g_v[Nc*Hc];
__device__ int   g_cnt[Ec];
__device__ int   g_tok[Ec*Nc];
__device__ float g_w[Ec*Nc];
__device__ float g_wninv[Ec];
__device__ float g_sig[Ec];

__device__ __half xhi[(size_t)Nc*Cc];
__device__ __half pqh[(size_t)Ec*Hc*Cc];
__device__ __half pkh[(size_t)Ec*Hc*Cc];
__device__ __half pvh[(size_t)Ec*Hc*Cc];
__device__ __half poh[(size_t)Ec*Cc*Hc];
__device__ __half g_ahi[Nc*Hc];
__device__ __nv_bfloat16 qshi[Nc*Hc], qslo[Nc*Hc];
__device__ __nv_bfloat16 kshi[Nc*Hc], kslo[Nc*Hc];
__device__ __nv_bfloat16 vshi[Nc*Hc], vslo[Nc*Hc];
__device__ float g_oa[KVS][Nc*Hc];
__device__ float g_mm[KVS][Nc], g_ll[KVS][Nc];
__device__ float g_cos[Tc*64], g_sin[Tc*64];

// ---------------- helpers ----------------
__device__ __forceinline__ uint32_t smem_u32(const void* p) {
    uint32_t a;
    asm("{ .reg .u64 t; cvta.to.shared.u64 t, %1; cvt.u32.u64 %0, t; }" : "=r"(a) : "l"(p));
    return a;
}
__device__ __forceinline__ void ldm4(uint32_t* r, uint32_t a) {
    asm volatile("ldmatrix.sync.aligned.m8n8.x4.shared.b16 {%0,%1,%2,%3}, [%4];"
        : "=r"(r[0]), "=r"(r[1]), "=r"(r[2]), "=r"(r[3]) : "r"(a));
}
__device__ __forceinline__ void ldm4t(uint32_t* r, uint32_t a) {
    asm volatile("ldmatrix.sync.aligned.m8n8.x4.trans.shared.b16 {%0,%1,%2,%3}, [%4];"
        : "=r"(r[0]), "=r"(r[1]), "=r"(r[2]), "=r"(r[3]) : "r"(a));
}
__device__ __forceinline__ void mma16816(float* d, const uint32_t* a, const uint32_t* b) {
    asm volatile("mma.sync.aligned.m16n8k16.row.col.f32.bf16.bf16.f32 "
        "{%0,%1,%2,%3},{%4,%5,%6,%7},{%8,%9},{%0,%1,%2,%3};"
        : "+f"(d[0]), "+f"(d[1]), "+f"(d[2]), "+f"(d[3])
        : "r"(a[0]), "r"(a[1]), "r"(a[2]), "r"(a[3]), "r"(b[0]), "r"(b[1]));
}
__device__ __forceinline__ void mma16816h(float* d, const uint32_t* a, const uint32_t* b) {
    asm volatile("mma.sync.aligned.m16n8k16.row.col.f32.f16.f16.f32 "
        "{%0,%1,%2,%3},{%4,%5,%6,%7},{%8,%9},{%0,%1,%2,%3};"
        : "+f"(d[0]), "+f"(d[1]), "+f"(d[2]), "+f"(d[3])
        : "r"(a[0]), "r"(a[1]), "r"(a[2]), "r"(a[3]), "r"(b[0]), "r"(b[1]));
}
__device__ __forceinline__ void cpa(uint32_t dst, const void* src, int zf) {
    asm volatile("cp.async.cg.shared.global [%0], [%1], 16, %2;"
        :: "r"(dst), "l"((unsigned long long)__cvta_generic_to_global(src)), "r"(zf) : "memory");
}
__device__ __forceinline__ void red2(float* p, float x, float y) {
    asm volatile("red.global.add.v2.f32 [%0], {%1,%2};"
        :: "l"((unsigned long long)__cvta_generic_to_global(p)), "f"(x), "f"(y) : "memory");
}
#define CP_COMMIT asm volatile("cp.async.commit_group;" ::: "memory")
#define CP_WAIT0  asm volatile("cp.async.wait_group 0;" ::: "memory")

// ---------------- prep: per-expert sim norms ----------------
__global__ void k_z0(const float* __restrict__ sim, const float* __restrict__ gates) {
    int e = blockIdx.x;
    int tid = threadIdx.x;
    float s = 0.f;
    for (int i = tid; i < Cc; i += 256) {
        float v = sim[(size_t)i*Ec + e];
        s += v*v;
    }
    __shared__ float red[8];
    int w = tid >> 5, lane = tid & 31;
    #pragma unroll
    for (int o = 16; o; o >>= 1) s += __shfl_xor_sync(0xffffffffu, s, o);
    if (lane == 0) red[w] = s;
    __syncthreads();
    if (tid == 0) {
        float t = 0.f;
        #pragma unroll
        for (int i = 0; i < 8; i++) t += red[i];
        g_wninv[e] = 1.0f / fmaxf(sqrtf(t), 1e-12f);
        g_sig[e] = 1.0f / (1.0f + expf(-gates[e]));
        g_cnt[e] = 0;
    }
}

// ---------------- big zeroing ----------------
__global__ void k_init(float* __restrict__ out) {
    int i = blockIdx.x * blockDim.x + threadIdx.x;
    int stride = gridDim.x * blockDim.x;
    float4 z = make_float4(0.f, 0.f, 0.f, 0.f);
    for (int j = i; j < Nc*Cc/4; j += stride) ((float4*)out)[j] = z;
    for (int j = i; j < Nc*Hc/4; j += stride) {
        ((float4*)g_q)[j] = z;
        ((float4*)g_k)[j] = z;
        ((float4*)g_v)[j] = z;
    }
}

// ---------------- rope table ----------------
__global__ void k_tab(const int* __restrict__ pid) {
    int idx = blockIdx.x * blockDim.x + threadIdx.x;
    int p = idx >> 6;
    int i = idx & 63;
    int t = pid[p];
    float ang = (float)t * exp2f(-(float)i * (13.28771237954945f / 64.0f));
    float s, c;
    sincosf(ang, &s, &c);
    g_cos[idx] = c;
    g_sin[idx] = s;
}

// ---------------- x -> fp16 (single) ----------------
__global__ void k_xhalf(const float* __restrict__ x) {
    #pragma unroll
    for (int j = 0; j < 4; j++) {
        int i = (blockIdx.x*4 + j)*256 + threadIdx.x;
        float4 v = ((const float4*)x)[i];
        ((__half2*)xhi)[i*2]   = __half2(__float2half_rn(v.x), __float2half_rn(v.y));
        ((__half2*)xhi)[i*2+1] = __half2(__float2half_rn(v.z), __float2half_rn(v.w));
    }
}

// ---------------- gating (R15 version) ----------------
__global__ void k_gate(const float* __restrict__ x, const float* __restrict__ sim) {
    int n0 = blockIdx.x * GT;
    float dot[GT][Ec];
    float ss[GT];
    #pragma unroll
    for (int j = 0; j < GT; j++) {
        ss[j] = 0.f;
        #pragma unroll
        for (int e = 0; e < Ec; e++) dot[j][e] = 0.f;
    }
    for (int i = threadIdx.x; i < Cc; i += 256) {
        float xv[GT];
        #pragma unroll
        for (int j = 0; j < GT; j++) {
            xv[j] = x[(size_t)(n0 + j)*Cc + i];
            ss[j] += xv[j]*xv[j];
        }
        const float4* s4 = (const float4*)(sim + (size_t)i*Ec);
        #pragma unroll
        for (int q = 0; q < 4; q++) {
            float4 sv = s4[q];
            #pragma unroll
            for (int j = 0; j < GT; j++) {
                dot[j][q*4+0] += xv[j]*sv.x;
                dot[j][q*4+1] += xv[j]*sv.y;
                dot[j][q*4+2] += xv[j]*sv.z;
                dot[j][q*4+3] += xv[j]*sv.w;
            }
        }
    }
    __shared__ float red[8][GT*Ec + GT];
    int wid = threadIdx.x >> 5, lane = threadIdx.x & 31;
    #pragma unroll
    for (int j = 0; j < GT; j++) {
        #pragma unroll
        for (int e = 0; e < Ec; e++) {
            float v = dot[j][e];
            #pragma unroll
            for (int o = 16; o; o >>= 1) v += __shfl_xor_sync(0xffffffffu, v, o);
            if (lane == 0) red[wid][j*Ec + e] = v;
        }
        float v = ss[j];
        #pragma unroll
        for (int o = 16; o; o >>= 1) v += __shfl_xor_sync(0xffffffffu, v, o);
        if (lane == 0) red[wid][GT*Ec + j] = v;
    }
    __syncthreads();
    if (threadIdx.x < GT*Ec + GT) {
        float s = 0.f;
        #pragma unroll
        for (int w = 0; w < 8; w++) s += red[w][threadIdx.x];
        red[0][threadIdx.x] = s;
    }
    __syncthreads();
    if (threadIdx.x < GT) {
        int j = threadIdx.x;
        int n = n0 + j;
        float xin = rsqrtf(fmaxf(red[0][GT*Ec + j], 1e-24f));
        float logitv[Ec], gatedv[Ec];
        int act = 0;
        #pragma unroll
        for (int e = 0; e < Ec; e++) {
            float lg = red[0][j*Ec + e] * xin * g_wninv[e] - g_sig[e];
            logitv[e] = lg;
            gatedv[e] = fmaxf(lg, 0.f);
            act += (lg > 0.f) ? 1 : 0;
        }
        unsigned mask = 0u;
        if (act > 0) {
            #pragma unroll
            for (int e = 0; e < Ec; e++) if (logitv[e] > 0.f) mask |= (1u << e);
        } else {
            int i1 = 0;
            #pragma unroll
            for (int e = 1; e < Ec; e++) if (logitv[e] > logitv[i1]) i1 = e;
            int i2 = (i1 == 0) ? 1 : 0;
            #pragma unroll
            for (int e = 0; e < Ec; e++)
                if (e != i1 && logitv[e] > logitv[i2]) i2 = e;
            mask = (1u << i1) | (1u << i2);
        }
        float m = -1e30f;
        #pragma unroll
        for (int e = 0; e < Ec; e++) if ((mask >> e) & 1u) m = fmaxf(m, gatedv[e]);
        float ssum = 0.f;
        float ex[Ec];
        #pragma unroll
        for (int e = 0; e < Ec; e++) {
            float t = ((mask >> e) & 1u) ? expf(gatedv[e] - m) : 0.f;
            ex[e] = t;
            ssum += t;
        }
        float sinv = 1.f / ssum;
        #pragma unroll
        for (int e = 0; e < Ec; e++) {
            if ((mask >> e) & 1u) {
                int p = atomicAdd(&g_cnt[e], 1);
                g_tok[e*Nc + p] = n;
                g_w[e*Nc + p]   = ex[e] * sinv;
            }
        }
    }
}

// ---------------- weight conversions (fp16 single) ----------------
__global__ void k_conv(const float* __restrict__ qp, const float* __restrict__ kp,
                       const float* __restrict__ vp, const float* __restrict__ op) {
    int y = blockIdx.y;
    __shared__ float tile[32][33];
    int e = blockIdx.x >> 8;
    int t = blockIdx.x & 255;
    int c0 = (t >> 2) * 32, h0 = (t & 3) * 32;
    int tx = threadIdx.x & 31, ty = threadIdx.x >> 5;
    if (y < 3) {
        const float* src = (y == 0) ? qp : (y == 1) ? kp : vp;
        __half* dh = (y == 0) ? pqh : (y == 1) ? pkh : pvh;
        #pragma unroll
        for (int cy = 0; cy < 32; cy += 8)
            tile[ty + cy][tx] = src[((size_t)e*Cc + c0 + ty + cy)*Hc + h0 + tx];
        __syncthreads();
        #pragma unroll
        for (int hy = 0; hy < 32; hy += 8) {
            float v = tile[tx][ty + hy];
            dh[((size_t)e*Hc + h0 + ty + hy)*Cc + c0 + tx] = __float2half_rn(v);
        }
    } else {
        #pragma unroll
        for (int hy = 0; hy < 32; hy += 8)
            tile[ty + hy][tx] = op[((size_t)e*Hc + h0 + ty + hy)*Cc + c0 + tx];
        __syncthreads();
        #pragma unroll
        for (int cy = 0; cy < 32; cy += 8) {
            float v = tile[tx][ty + cy];
            poh[((size_t)e*Cc + c0 + ty + cy)*Hc + h0 + tx] = __float2half_rn(v);
        }
    }
}

// ---------------- fp16 1-product grouped QKV GEMM ----------------
#define STG_A 10240
#define STG_SZ (2*STG_A)      // Ah, Bh
__global__ __launch_bounds__(256, 2) void k_qkv_mma() {
    extern __shared__ char smem[];
    int e = blockIdx.y;
    int cnt = g_cnt[e];
    int m0 = blockIdx.x * 128;
    if (m0 >= cnt) return;
    int sel = blockIdx.z % 3;
    int ksp = blockIdx.z / 3;
    const __half* BH;
    float* dst;
    if (sel == 0)      { BH = pqh; dst = g_q; }
    else if (sel == 1) { BH = pkh; dst = g_k; }
    else               { BH = pvh; dst = g_v; }

    int* sTok = (int*)smem;
    float* sW = (float*)(smem + 512);
    uint32_t tiles = smem_u32(smem) + 1024;
    int tid = threadIdx.x;

    if (tid < 128) {
        int i = m0 + tid;
        if (i < cnt) { sTok[tid] = g_tok[e*Nc + i]; sW[tid] = g_w[e*Nc + i]; }
        else         { sTok[tid] = -1;               sW[tid] = 0.f; }
    }
    __syncthreads();

    int lrow = tid >> 1, lc = (tid & 1) * 2;
    int ltok = sTok[lrow];
    int zf = (ltok >= 0) ? 16 : 0;
    int kbase0 = ksp * (Cc/2);
    const __half* aHp = xhi + (size_t)(ltok < 0 ? 0 : ltok)*Cc + kbase0 + lc*8;
    const __half* bHp = BH + ((size_t)e*Hc + lrow)*Cc + kbase0 + lc*8;
    uint32_t loff = lrow*80 + lc*16;

    auto loadStage = [&](int s) {
        uint32_t base = tiles + (s & 1) * STG_SZ;
        int k0 = s * 32;
        cpa(base + loff,              aHp + k0, zf);
        cpa(base + loff + 16,         aHp + k0 + 8, zf);
        cpa(base + STG_A + loff,      bHp + k0, 16);
        cpa(base + STG_A + loff + 16, bHp + k0 + 8, 16);
        CP_COMMIT;
    };

    int w = tid >> 5, lane = tid & 31;
    int wr = w & 3, wc = w >> 2;
    int aRowL = wr*32 + (lane & 15);
    int aCB  = lane >> 4;
    int bRowL = (lane & 7) + ((lane >> 4) << 3);
    int bCB  = (lane >> 3) & 1;

    float d[2][8][4];
    #pragma unroll
    for (int mt = 0; mt < 2; mt++)
        #pragma unroll
        for (int nt = 0; nt < 8; nt++)
            #pragma unroll
            for (int q = 0; q < 4; q++) d[mt][nt][q] = 0.f;

    const int NS = (Cc/2)/32;
    loadStage(0);
    for (int s = 0; s < NS; s++) {
        CP_WAIT0;
        __syncthreads();
        if (s + 1 < NS) loadStage(s + 1);
        uint32_t base = tiles + (s & 1)*STG_SZ;
        uint32_t bbase = base + STG_A;
        #pragma unroll
        for (int kc = 0; kc < 2; kc++) {
            uint32_t ah[2][4];
            #pragma unroll
            for (int mt = 0; mt < 2; mt++) {
                int r = aRowL + mt*16;
                ldm4(ah[mt], base + r*80 + (((kc << 1) + aCB) << 4));
            }
            #pragma unroll
            for (int np = 0; np < 4; np++) {
                int r = wc*64 + np*16 + bRowL;
                uint32_t bh[4];
                ldm4(bh, bbase + r*80 + (((kc << 1) + bCB) << 4));
                #pragma unroll
                for (int mt = 0; mt < 2; mt++)
                    #pragma unroll
                    for (int i = 0; i < 2; i++)
                        mma16816h(d[mt][np*2 + i], ah[mt], bh + 2*i);
            }
        }
    }

    #pragma unroll
    for (int mt = 0; mt < 2; mt++) {
        int r0 = wr*32 + mt*16 + (lane >> 2);
        int r1 = r0 + 8;
        int t0 = sTok[r0], t1 = sTok[r1];
        float w0 = sW[r0], w1 = sW[r1];
        #pragma unroll
        for (int nt = 0; nt < 8; nt++) {
            int col = wc*64 + nt*8 + (lane & 3)*2;
            if (t0 >= 0) red2(dst + (size_t)t0*Hc + col, d[mt][nt][0]*w0, d[mt][nt][1]*w0);
            if (t1 >= 0) red2(dst + (size_t)t1*Hc + col, d[mt][nt][2]*w1, d[mt][nt][3]*w1);
        }
    }
}

// ---------------- RoPE (table lookup) + bf16 hi/lo split ----------------
__global__ void k_rope() {
    int idx = blockIdx.x * blockDim.x + threadIdx.x;
    if (idx >= Nc*64) return;
    int n = idx >> 6;
    int i = idx & 63;
    int p = n & (Tc - 1);
    float c = g_cos[p*64 + i];
    float s = g_sin[p*64 + i];
    size_t base = (size_t)n * Hc;
    float q0 = g_q[base + i], q1 = g_q[base + i + 64];
    float k0 = g_k[base + i], k1 = g_k[base + i + 64];
    float v0 = g_v[base + i], v1 = g_v[base + i + 64];
    float qa = q0*c - q1*s, qb = q1*c + q0*s;
    float ka = k0*c - k1*s, kb = k1*c + k0*s;
    __nv_bfloat16 h;
    h = __float2bfloat16_rn(qa); qshi[base+i] = h;    qslo[base+i]    = __float2bfloat16_rn(qa - __bfloat162float(h));
    h = __float2bfloat16_rn(qb); qshi[base+i+64] = h; qslo[base+i+64] = __float2bfloat16_rn(qb - __bfloat162float(h));
    h = __float2bfloat16_rn(ka); kshi[base+i] = h;    kslo[base+i]    = __float2bfloat16_rn(ka - __bfloat162float(h));
    h = __float2bfloat16_rn(kb); kshi[base+i+64] = h; kslo[base+i+64] = __float2bfloat16_rn(kb - __bfloat162float(h));
    h = __float2bfloat16_rn(v0); vshi[base+i] = h;    vslo[base+i]    = __float2bfloat16_rn(v0 - __bfloat162float(h));
    h = __float2bfloat16_rn(v1); vshi[base+i+64] = h; vslo[base+i+64] = __float2bfloat16_rn(v1 - __bfloat162float(h));
}

// ---------------- MMA flash attention, split-KV x4 (bf16 3-product) ----------------
__global__ __launch_bounds__(256, 1) void k_attn_mma() {
    extern __shared__ char smem[];
    int qb = blockIdx.x;
    int b  = blockIdx.y;
    int zz = blockIdx.z;
    int q0 = qb * 128;
    uint32_t sQ = smem_u32(smem);
    uint32_t sKV = sQ + 65536;
    int tid = threadIdx.x, w = tid >> 5, lane = tid & 31;

    int nkt_tot = 2*qb + 2;
    int kt0 = (nkt_tot * zz) / KVS;
    int kt1 = (nkt_tot * (zz + 1)) / KVS;

    {
        int qrow = tid >> 1;
        int c4 = (tid & 1) * 4;
        const __nv_bfloat16* qh = qshi + ((size_t)(b*Tc + q0 + qrow))*Hc;
        const __nv_bfloat16* ql = qslo + ((size_t)(b*Tc + q0 + qrow))*Hc;
        #pragma unroll
        for (int sub = 0; sub < 2; sub++) {
            #pragma unroll
            for (int u = 0; u < 4; u++) {
                int c = c4 + u;
                uint32_t off = sub*16384 + qrow*128 + ((c ^ (qrow & 7)) << 4);
                cpa(sQ + off,         qh + sub*64 + c*8, 16);
                cpa(sQ + 32768 + off, ql + sub*64 + c*8, 16);
            }
        }
        CP_COMMIT;
    }

    int krow = tid >> 2;
    int part = tid & 3;
    const __nv_bfloat16* kvsrc =
        (part == 0) ? kshi : (part == 1) ? kslo : (part == 2) ? vshi : vslo;
    auto loadKV = [&](int kt) {
        uint32_t base = sKV + (kt & 1)*65536 + part*16384;
        const __nv_bfloat16* src = kvsrc + ((size_t)(b*Tc + kt*64 + krow))*Hc;
        #pragma unroll
        for (int sub = 0; sub < 2; sub++) {
            #pragma unroll
            for (int c = 0; c < 8; c++) {
                cpa(base + sub*8192 + krow*128 + ((c ^ (krow & 7)) << 4),
                    src + sub*64 + c*8, 16);
            }
        }
        CP_COMMIT;
    };

    const float scale = 0.08838834764831845f;
    float o[16][4];
    #pragma unroll
    for (int nt = 0; nt < 16; nt++)
        #pragma unroll
        for (int q = 0; q < 4; q++) o[nt][q] = 0.f;
    float m0 = -1e30f, m1 = -1e30f, l0 = 0.f, l1 = 0.f;

    int aRow = w*16 + (lane & 15);
    int aCB  = lane >> 4;
    int bRow = (lane & 7) + ((lane >> 4) << 3);
    int bCB  = (lane >> 3) & 1;
    int rowg0 = q0 + w*16 + (lane >> 2);
    int rowg1 = rowg0 + 8;

    if (kt0 < kt1) loadKV(kt0);
    for (int kt = kt0; kt < kt1; kt++) {
        CP_WAIT0;
        __syncthreads();
        if (kt + 1 < kt1) loadKV(kt + 1);
        uint32_t kbase = sKV + (kt & 1)*65536;

        float sAcc[8][4];
        #pragma unroll
        for (int nt = 0; nt < 8; nt++)
            #pragma unroll
            for (int q = 0; q < 4; q++) sAcc[nt][q] = 0.f;
        #pragma unroll
        for (int sub = 0; sub < 2; sub++) {
            #pragma unroll
            for (int kc = 0; kc < 4; kc++) {
                uint32_t ah[4], al[4];
                uint32_t ad = sQ + sub*16384 + aRow*128 + ((((kc << 1) + aCB) ^ (aRow & 7)) << 4);
                ldm4(ah, ad);
                ldm4(al, ad + 32768);
                #pragma unroll
                for (int nb = 0; nb < 2; nb++) {
                    uint32_t bh0[4], bl0[4], bh1[4], bl1[4];
                    int r0 = bRow + (2*nb)*16;
                    int r1 = bRow + (2*nb + 1)*16;
                    uint32_t bd0 = kbase + sub*8192 + r0*128 + ((((kc << 1) + bCB) ^ (r0 & 7)) << 4);
                    uint32_t bd1 = kbase + sub*8192 + r1*128 + ((((kc << 1) + bCB) ^ (r1 & 7)) << 4);
                    ldm4(bh0, bd0);
                    ldm4(bl0, bd0 + 16384);
                    ldm4(bh1, bd1);
                    ldm4(bl1, bd1 + 16384);
                    float* a0 = sAcc[4*nb + 0];
                    float* a1 = sAcc[4*nb + 1];
                    float* a2 = sAcc[4*nb + 2];
                    float* a3 = sAcc[4*nb + 3];
                    mma16816(a0, ah, bh0 + 0); mma16816(a1, ah, bh0 + 2);
                    mma16816(a2, ah, bh1 + 0); mma16816(a3, ah, bh1 + 2);
                    mma16816(a0, ah, bl0 + 0); mma16816(a1, ah, bl0 + 2);
                    mma16816(a2, ah, bl1 + 0); mma16816(a3, ah, bl1 + 2);
                    mma16816(a0, al, bh0 + 0); mma16816(a1, al, bh0 + 2);
                    mma16816(a2, al, bh1 + 0); mma16816(a3, al, bh1 + 2);
                }
            }
        }

        int k0 = kt*64;
        bool diag = (kt >= 2*qb);
        #pragma unroll
        for (int nt = 0; nt < 8; nt++) {
            int cbase = k0 + nt*8 + (lane & 3)*2;
            #pragma unroll
            for (int q = 0; q < 4; q++) {
                float v = sAcc[nt][q] * scale;
                if (diag) {
                    int col = cbase + (q & 1);
                    int row = (q < 2) ? rowg0 : rowg1;
                    if (col > row) v = -1e30f;
                }
                sAcc[nt][q] = v;
            }
        }

        float rm0 = -1e30f, rm1 = -1e30f;
        #pragma unroll
        for (int nt = 0; nt < 8; nt++) {
            rm0 = fmaxf(rm0, fmaxf(sAcc[nt][0], sAcc[nt][1]));
            rm1 = fmaxf(rm1, fmaxf(sAcc[nt][2], sAcc[nt][3]));
        }
        #pragma unroll
        for (int off = 1; off < 4; off <<= 1) {
            rm0 = fmaxf(rm0, __shfl_xor_sync(0xffffffffu, rm0, off));
            rm1 = fmaxf(rm1, __shfl_xor_sync(0xffffffffu, rm1, off));
        }
        float mn0 = fmaxf(m0, rm0), mn1 = fmaxf(m1, rm1);
        float al0 = __expf(m0 - mn0), al1 = __expf(m1 - mn1);
        float ps0 = 0.f, ps1 = 0.f;
        #pragma unroll
        for (int nt = 0; nt < 8; nt++) {
            sAcc[nt][0] = __expf(sAcc[nt][0] - mn0);
            sAcc[nt][1] = __expf(sAcc[nt][1] - mn0);
            sAcc[nt][2] = __expf(sAcc[nt][2] - mn1);
            sAcc[nt][3] = __expf(sAcc[nt][3] - mn1);
            ps0 += sAcc[nt][0] + sAcc[nt][1];
            ps1 += sAcc[nt][2] + sAcc[nt][3];
        }
        #pragma unroll
        for (int off = 1; off < 4; off <<= 1) {
            ps0 += __shfl_xor_sync(0xffffffffu, ps0, off);
            ps1 += __shfl_xor_sync(0xffffffffu, ps1, off);
        }
        l0 = l0*al0 + ps0;
        l1 = l1*al1 + ps1;
        m0 = mn0;
        m1 = mn1;
        #pragma unroll
        for (int nt = 0; nt < 16; nt++) {
            o[nt][0] *= al0; o[nt][1] *= al0;
            o[nt][2] *= al1; o[nt][3] *= al1;
        }

        #pragma unroll
        for (int ks = 0; ks < 4; ks++) {
            uint32_t ph[4], pl[4];
            #pragma unroll
            for (int hq = 0; hq < 2; hq++) {
                int nt = 2*ks + hq;
                float p0 = sAcc[nt][0], p1 = sAcc[nt][1];
                float p2 = sAcc[nt][2], p3 = sAcc[nt][3];
                __nv_bfloat16 b0 = __float2bfloat16_rn(p0), b1 = __float2bfloat16_rn(p1);
                __nv_bfloat16 b2 = __float2bfloat16_rn(p2), b3 = __float2bfloat16_rn(p3);
                __nv_bfloat162 hh01(b0, b1), hh23(b2, b3);
                ph[0 + hq*2] = *(uint32_t*)&hh01;
                ph[1 + hq*2] = *(uint32_t*)&hh23;
                __nv_bfloat162 ll01(__float2bfloat16_rn(p0 - __bfloat162float(b0)),
                                    __float2bfloat16_rn(p1 - __bfloat162float(b1)));
                __nv_bfloat162 ll23(__float2bfloat16_rn(p2 - __bfloat162float(b2)),
                                    __float2bfloat16_rn(p3 - __bfloat162float(b3)));
                pl[0 + hq*2] = *(uint32_t*)&ll01;
                pl[1 + hq*2] = *(uint32_t*)&ll23;
            }
            int vrow = ks*16 + (lane & 15);
            #pragma unroll
            for (int hp = 0; hp < 4; hp++) {
                int ht0 = 2*hp, ht1 = 2*hp + 1;
                int sub0 = ht0 >> 2, sub1 = ht1 >> 2;
                int cl0 = (ht0 & 3)*2 + (lane >> 4);
                int cl1 = (ht1 & 3)*2 + (lane >> 4);
                uint32_t vd0 = kbase + 32768 + sub0*8192 + vrow*128 + ((cl0 ^ (vrow & 7)) << 4);
                uint32_t vd1 = kbase + 32768 + sub1*8192 + vrow*128 + ((cl1 ^ (vrow & 7)) << 4);
                uint32_t vh0[4], vl0[4], vh1[4], vl1[4];
                ldm4t(vh0, vd0);
                ldm4t(vl0, vd0 + 16384);
                ldm4t(vh1, vd1);
                ldm4t(vl1, vd1 + 16384);
                float* a0 = o[ht0*2 + 0];
                float* a1 = o[ht0*2 + 1];
                float* a2 = o[ht1*2 + 0];
                float* a3 = o[ht1*2 + 1];
                mma16816(a0, ph, vh0 + 0); mma16816(a1, ph, vh0 + 2);
                mma16816(a2, ph, vh1 + 0); mma16816(a3, ph, vh1 + 2);
                mma16816(a0, ph, vl0 + 0); mma16816(a1, ph, vl0 + 2);
                mma16816(a2, ph, vl1 + 0); mma16816(a3, ph, vl1 + 2);
                mma16816(a0, pl, vh0 + 0); mma16816(a1, pl, vh0 + 2);
                mma16816(a2, pl, vh1 + 0); mma16816(a3, pl, vh1 + 2);
            }
        }
    }

    float* oa = g_oa[zz];
    float* gm = g_mm[zz];
    float* gl = g_ll[zz];
    int n0g = b*Tc + rowg0;
    int n1g = b*Tc + rowg1;
    if ((lane & 3) == 0) {
        gm[n0g] = m0; gl[n0g] = l0;
        gm[n1g] = m1; gl[n1g] = l1;
    }
    size_t ga0 = (size_t)n0g*Hc;
    size_t ga1 = (size_t)n1g*Hc;
    #pragma unroll
    for (int nt = 0; nt < 16; nt++) {
        int col = nt*8 + (lane & 3)*2;
        *(float2*)(oa + ga0 + col) = make_float2(o[nt][0], o[nt][1]);
        *(float2*)(oa + ga1 + col) = make_float2(o[nt][2], o[nt][3]);
    }
}

// ---------------- combine split-KV partials (x4) -> fp16 (single) ----------------
__global__ void k_combine() {
    int idx = blockIdx.x * blockDim.x + threadIdx.x;
    int n = idx >> 5;
    int c4 = (idx & 31) * 4;
    float mv[KVS], lv[KVS];
    float M = -1e30f;
    #pragma unroll
    for (int z = 0; z < KVS; z++) {
        mv[z] = g_mm[z][n];
        lv[z] = g_ll[z][n];
        M = fmaxf(M, mv[z]);
    }
    float wz[KVS];
    float L = 0.f;
    #pragma unroll
    for (int z = 0; z < KVS; z++) {
        wz[z] = __expf(mv[z] - M);
        L += lv[z]*wz[z];
    }
    float li = 1.0f / L;
    float v0 = 0.f, v1 = 0.f, v2 = 0.f, v3 = 0.f;
    #pragma unroll
    for (int z = 0; z < KVS; z++) {
        float4 oz = *(float4*)(g_oa[z] + (size_t)n*Hc + c4);
        v0 += oz.x*wz[z]; v1 += oz.y*wz[z];
        v2 += oz.z*wz[z]; v3 += oz.w*wz[z];
    }
    v0 *= li; v1 *= li; v2 *= li; v3 *= li;
    ((__half2*)(g_ahi + (size_t)n*Hc + c4))[0] = __half2(__float2half_rn(v0), __float2half_rn(v1));
    ((__half2*)(g_ahi + (size_t)n*Hc + c4))[1] = __half2(__float2half_rn(v2), __float2half_rn(v3));
}

// ---------------- fp16 1-product grouped O-proj GEMM ----------------
// A resident: Ah kh=0,1 (2 x 16KB). B: 2 stages x (kh 2 x 16KB).
__global__ __launch_bounds__(256, 1) void k_oproj_mma(float* __restrict__ out) {
    extern __shared__ char smem[];
    int e = blockIdx.y;
    int cnt = g_cnt[e];
    int m0 = blockIdx.x * 128;
    if (m0 >= cnt) return;
    int nc0 = blockIdx.z * 8, nc1 = nc0 + 8;

    int* sTok = (int*)smem;
    float* sW = (float*)(smem + 512);
    uint32_t tiles = smem_u32(smem) + 1024;
    int tid = threadIdx.x;

    if (tid < 128) {
        int i = m0 + tid;
        if (i < cnt) { sTok[tid] = g_tok[e*Nc + i]; sW[tid] = g_w[e*Nc + i]; }
        else         { sTok[tid] = -1;               sW[tid] = 0.f; }
    }
    __syncthreads();

    int lrow = tid >> 1;
    int lc0 = (tid & 1) * 4;
    int ltok = sTok[lrow];
    int zf = (ltok >= 0) ? 16 : 0;
    uint32_t loff[4];
    #pragma unroll
    for (int u = 0; u < 4; u++) {
        int c = lc0 + u;
        loff[u] = lrow*128 + ((c ^ (lrow & 7)) << 4);
    }
    {
        const __half* aH = g_ahi + (size_t)(ltok < 0 ? 0 : ltok)*Hc;
        #pragma unroll
        for (int kh = 0; kh < 2; kh++) {
            #pragma unroll
            for (int u = 0; u < 4; u++) {
                int c = lc0 + u;
                cpa(tiles + kh*16384 + loff[u], aH + kh*64 + c*8, zf);
            }
        }
        CP_COMMIT;
    }
    const __half* oH = poh + ((size_t)e*Cc + lrow)*Hc;
    auto loadB = [&](int nc) {
        uint32_t base = tiles + 32768 + (nc & 1)*32768;
        size_t ro = (size_t)nc*128*Hc;
        #pragma unroll
        for (int kh = 0; kh < 2; kh++) {
            #pragma unroll
            for (int u = 0; u < 4; u++) {
                int c = lc0 + u;
                cpa(base + kh*16384 + loff[u], oH + ro + kh*64 + c*8, 16);
            }
        }
        CP_COMMIT;
    };

    int w = tid >> 5, lane = tid & 31;
    int wr = w & 3, wc = w >> 2;
    int aRow  = wr*32 + (lane & 15);
    int aCB   = lane >> 4;
    int bRowB = wc*64 + (lane & 7) + ((lane >> 4) << 3);
    int bCB   = (lane >> 3) & 1;

    int et0[2], et1[2];
    float ew0[2], ew1[2];
    #pragma unroll
    for (int mt = 0; mt < 2; mt++) {
        int r0 = wr*32 + mt*16 + (lane >> 2);
        et0[mt] = sTok[r0]; ew0[mt] = sW[r0];
        et1[mt] = sTok[r0 + 8]; ew1[mt] = sW[r0 + 8];
    }

    loadB(nc0);
    for (int nc = nc0; nc < nc1; nc++) {
        CP_WAIT0;
        __syncthreads();
        if (nc + 1 < nc1) loadB(nc + 1);

        float d[2][8][4];
        #pragma unroll
        for (int mt = 0; mt < 2; mt++)
            #pragma unroll
            for (int nt = 0; nt < 8; nt++)
                #pragma unroll
                for (int q = 0; q < 4; q++) d[mt][nt][q] = 0.f;

        uint32_t bbase = tiles + 32768 + (nc & 1)*32768;
        #pragma unroll
        for (int kh = 0; kh < 2; kh++) {
            #pragma unroll
            for (int kc = 0; kc < 4; kc++) {
                uint32_t ah[2][4];
                #pragma unroll
                for (int mt = 0; mt < 2; mt++) {
                    int r = aRow + mt*16;
                    ldm4(ah[mt], tiles + kh*16384 + r*128 + ((((kc << 1) + aCB) ^ (r & 7)) << 4));
                }
                #pragma unroll
                for (int np = 0; np < 4; np++) {
                    int r = bRowB + np*16;
                    uint32_t bh[4];
                    ldm4(bh, bbase + kh*16384 + r*128 + ((((kc << 1) + bCB) ^ (r & 7)) << 4));
                    #pragma unroll
                    for (int mt = 0; mt < 2; mt++)
                        #pragma unroll
                        for (int i = 0; i < 2; i++)
                            mma16816h(d[mt][np*2 + i], ah[mt], bh + 2*i);
                }
            }
        }

        #pragma unroll
        for (int mt = 0; mt < 2; mt++) {
            #pragma unroll
            for (int nt = 0; nt < 8; nt++) {
                int col = nc*128 + wc*64 + nt*8 + (lane & 3)*2;
                if (et0[mt] >= 0) red2(out + (size_t)et0[mt]*Cc + col, d[mt][nt][0]*ew0[mt], d[mt][nt][1]*ew0[mt]);
                if (et1[mt] >= 0) red2(out + (size_t)et1[mt]*Cc + col, d[mt][nt][2]*ew1[mt], d[mt][nt][3]*ew1[mt]);
            }
        }
    }
}

// ---------------- launch (stream fork/join overlap) ----------------
extern "C" void kernel_launch(void* const* d_in, const int* in_sizes, int n_in,
                              void* d_out, int out_size) {
    const float* x     = (const float*)d_in[0];
    const int*   pid   = (const int*)  d_in[1];
    const float* sim   = (const float*)d_in[2];
    const float* gates = (const float*)d_in[3];
    const float* qp    = (const float*)d_in[4];
    const float* kp    = (const float*)d_in[5];
    const float* vp    = (const float*)d_in[6];
    const float* op    = (const float*)d_in[7];
    float* out = (float*)d_out;

    const int SMEM_QKV  = 1024 + 2*STG_SZ;          // 41984
    const int SMEM_OP   = 1024 + 32768 + 65536;     // 99328
    const int SMEM_ATTN = 65536 + 2*65536;          // 196608
    static cudaStream_t s1 = nullptr, s2 = nullptr;
    static cudaEvent_t ev0, ev1, ev2;
    if (!s1) {
        cudaStreamCreateWithFlags(&s1, cudaStreamNonBlocking);
        cudaStreamCreateWithFlags(&s2, cudaStreamNonBlocking);
        cudaEventCreateWithFlags(&ev0, cudaEventDisableTiming);
        cudaEventCreateWithFlags(&ev1, cudaEventDisableTiming);
        cudaEventCreateWithFlags(&ev2, cudaEventDisableTiming);
        cudaFuncSetAttribute(k_qkv_mma,   cudaFuncAttributeMaxDynamicSharedMemorySize, SMEM_QKV);
        cudaFuncSetAttribute(k_oproj_mma, cudaFuncAttributeMaxDynamicSharedMemorySize, SMEM_OP);
        cudaFuncSetAttribute(k_attn_mma,  cudaFuncAttributeMaxDynamicSharedMemorySize, SMEM_ATTN);
    }

    // fork
    cudaEventRecord(ev0, 0);
    cudaStreamWaitEvent(s1, ev0, 0);
    cudaStreamWaitEvent(s2, ev0, 0);

    // s1: weight conversion
    k_conv <<<dim3(4096, 4), 256, 0, s1>>>(qp, kp, vp, op);
    cudaEventRecord(ev1, s1);

    // s2: zeroing + rope table + x fp16
    k_init  <<<2048, 256, 0, s2>>>(out);
    k_xhalf <<<4096, 256, 0, s2>>>(x);
    k_tab   <<<(Tc*64)/256, 256, 0, s2>>>(pid);
    cudaEventRecord(ev2, s2);

    // s0: gating chain
    k_z0   <<<Ec, 256>>>(sim, gates);
    k_gate <<<Nc/GT, 256>>>(x, sim);

    // join
    cudaStreamWaitEvent(0, ev1, 0);
    cudaStreamWaitEvent(0, ev2, 0);

    k_qkv_mma<<<dim3(Nc/128, Ec, 6), 256, SMEM_QKV>>>();
    k_rope <<<(Nc*64)/256, 256>>>();
    k_attn_mma<<<dim3(Tc/128, Bc, KVS), 256, SMEM_ATTN>>>();
    k_combine<<<(Nc*32)/256, 256>>>();
    k_oproj_mma<<<dim3(Nc/128, Ec, 2), 256, SMEM_OP>>>(out);
}